// round 6
// baseline (speedup 1.0000x reference)
#include <cuda_runtime.h>

// FiringRateModel: T-step scalar-feedback linear recurrence, B independent chains.
//
// y = D∘u state (u = v.*w/100). Two-step-deferred reduction:
//   z(t)   = W(t-2) + c_t*SA + c_{t-1}*SDA + f(t-1)*SB + f(t-2)*SDB
//   f(t)   = max(0, 200 - 400/(1 + 2^(K*poly(z))))     (== relu(200*tanh(poly)))
//   y(t)   = D∘y(t-1) + c_t*DA + f(t-1)*DB             (wide, 3 f2-ops/pair)
//   W(t)   = sum(D∘y(t))  -> mul+tree+2 shfl, consumed at t+2
//
// The W reduction (tree + two 26-cyc shfls) has ~2 full step-periods of slack,
// so the serial loop is only: fma(f*SB) -> Estrin -> ex2 -> rcp -> fma -> max.
// c-terms are folded into the prefetch ring (c_t, c_{t-1} both known ahead).
//
// R=4 lanes/chain (8 f32x2 pairs/lane) -> 32768 threads = 1024 warps = 2/SMSP.

#define TPB 256

typedef unsigned long long u64p;

__device__ __forceinline__ u64p pk2(float lo, float hi) {
    u64p r;
    asm("mov.b64 %0, {%1,%2};" : "=l"(r) : "r"(__float_as_uint(lo)), "r"(__float_as_uint(hi)));
    return r;
}
__device__ __forceinline__ void upk2(u64p v, float &lo, float &hi) {
    unsigned int l, h;
    asm("mov.b64 {%0,%1}, %2;" : "=r"(l), "=r"(h) : "l"(v));
    lo = __uint_as_float(l); hi = __uint_as_float(h);
}
__device__ __forceinline__ u64p f2fma(u64p a, u64p b, u64p c) {
    u64p d;
    asm("fma.rn.f32x2 %0, %1, %2, %3;" : "=l"(d) : "l"(a), "l"(b), "l"(c));
    return d;
}
__device__ __forceinline__ u64p f2mul(u64p a, u64p b) {
    u64p d;
    asm("mul.rn.f32x2 %0, %1, %2;" : "=l"(d) : "l"(a), "l"(b));
    return d;
}
__device__ __forceinline__ u64p f2add(u64p a, u64p b) {
    u64p d;
    asm("add.rn.f32x2 %0, %1, %2;" : "=l"(d) : "l"(a), "l"(b));
    return d;
}
__device__ __forceinline__ float ex2a(float x) {
    float r; asm("ex2.approx.f32 %0, %1;" : "=f"(r) : "f"(x)); return r;
}
__device__ __forceinline__ float rcpa(float x) {
    float r; asm("rcp.approx.f32 %0, %1;" : "=f"(r) : "f"(x)); return r;
}

__global__ void __launch_bounds__(TPB, 1)
fr_kernel(const float* __restrict__ cur,   // [T, B]
          const float* __restrict__ fs0,   // [B]
          const float* __restrict__ av,    // [N]
          const float* __restrict__ bv,    // [N]
          const float* __restrict__ wv,    // [N]
          const float* __restrict__ dsv,   // [N]
          const float* __restrict__ pc,    // [6]
          const float* __restrict__ gbp,   // [1]
          float* __restrict__ out,         // [T, B]
          int T, int B)
{
    int tid = blockIdx.x * TPB + threadIdx.x;
    int chain = tid >> 2;        // one chain per 4 lanes
    int r = tid & 3;
    if (chain >= B) return;
    int nb = r * 16;             // 16 neurons = 8 packed pairs per lane

    // Polynomial coefficients, squared per reference, with K = 2*log2(e)
    // folded in so q = K*poly(x) and tanh = 1 - 2/(1+2^q).
    const float K = 2.885390081777927f;
    float C0 = K * pc[0] * pc[0], C1 = K * pc[1] * pc[1], C2 = K * pc[2] * pc[2];
    float C3 = K * pc[3] * pc[3], C4 = K * pc[4] * pc[4], C5 = K * pc[5] * pc[5];
    float gb = gbp[0] * 0.01f;

    // Per-lane constants. u = v.*w/100: A' = a*w/100, B' = 10*b*w, D = 1-ds.
    // Pre-multiplied: DA = D∘A', DB = D∘B'.
    u64p D[8], DA[8], DB[8], Y[8];
    float sap = 0.f, sbp = 0.f, sdap = 0.f, sdbp = 0.f;
    #pragma unroll
    for (int j = 0; j < 8; j++) {
        int n0 = nb + 2 * j;
        float w0 = wv[n0],            w1 = wv[n0 + 1];
        float d0 = 1.f - dsv[n0],     d1 = 1.f - dsv[n0 + 1];
        float a0 = av[n0] * w0 * 0.01f, a1 = av[n0 + 1] * w1 * 0.01f;
        float b0 = 10.f * bv[n0] * w0,  b1 = 10.f * bv[n0 + 1] * w1;
        D[j]  = pk2(d0, d1);
        DA[j] = pk2(d0 * a0, d1 * a1);
        DB[j] = pk2(d0 * b0, d1 * b1);
        Y[j]  = 0ull;
        sap  += a0 + a1;
        sbp  += b0 + b1;
        sdap += d0 * a0 + d1 * a1;
        sdbp += d0 * b0 + d1 * b1;
    }
    #pragma unroll
    for (int m = 1; m <= 2; m <<= 1) {
        sap  += __shfl_xor_sync(0xffffffffu, sap,  m);
        sbp  += __shfl_xor_sync(0xffffffffu, sbp,  m);
        sdap += __shfl_xor_sync(0xffffffffu, sdap, m);
        sdbp += __shfl_xor_sync(0xffffffffu, sdbp, m);
    }
    const float SA = sap, SB = sbp, SDA = sdap, SDB = sdbp;

    float f1 = fs0[chain];       // f(t-1)
    float fx2 = 0.f;             // f(t-2)  (t=0 convention: 0)
    float Wm1 = 0.f, Wm2 = 0.f;  // W(t-1), W(t-2)  (y(-1)=y(-2)=0)

    const float* cp = cur + chain;         // initial ring fill
    const float* lp = cp + (size_t)8 * B;  // prefetch pointer -> c_{t+8}
    float* op = out + chain;

    // Prefetch rings: cb[i] = c_i (raw, wide path),
    //                 cs[i] = c_i*SA + c_{i-1}*SDA - gb  (serial path, hoisted)
    float cb[8], cs[8];
    {
        float clast = 0.f;       // c_{-1} = 0
        #pragma unroll
        for (int i = 0; i < 8; i++) {
            cb[i] = cp[(size_t)i * B];
            cs[i] = fmaf(cb[i], SA, fmaf(clast, SDA, -gb));
            clast = cb[i];
        }
    }
    float clast = cb[7];         // newest prefetched current (c_7)

    // One step. craw = c_t, cpre = c_t*SA + c_{t-1}*SDA - gb.
    #define FR_STEP(craw, cpre)                                                \
    {                                                                          \
        /* serial: z = W(t-2) + cpre + f(t-2)*SDB + f(t-1)*SB */               \
        float base = fmaf(fx2, SDB, Wm2 + (cpre));                             \
        float x = fmaf(f1, SB, base);                                          \
        float x2 = x * x;                                                      \
        float x4 = x2 * x2;                                                    \
        float e01 = fmaf(C1, x, C0);                                           \
        float e23 = fmaf(C3, x, C2);                                           \
        float e45 = fmaf(C5, x, C4);                                           \
        float q = fmaf(x2, e23, e01);                                          \
        q = fmaf(x4, e45, q);                          /* q = K*poly(x) */     \
        float e = ex2a(q);                                                     \
        float fn = fmaf(rcpa(e + 1.f), -400.f, 200.f);                         \
        fn = fmaxf(fn, 0.f);                                                   \
        /* wide path (uses f(t-1), c_t; independent of fn) */                  \
        u64p c2 = pk2((craw), (craw));                                         \
        u64p f2r = pk2(f1, f1);                                                \
        _Pragma("unroll")                                                      \
        for (int j = 0; j < 8; j++) {                                          \
            u64p t1 = f2fma(DB[j], f2r, f2mul(DA[j], c2));                     \
            Y[j] = f2fma(D[j], Y[j], t1);                                      \
        }                                                                      \
        /* W(t) = sum(D∘y(t)) -> consumed at t+2 (2 periods of slack) */       \
        u64p g0 = f2add(f2add(f2mul(D[0], Y[0]), f2mul(D[1], Y[1])),           \
                        f2add(f2mul(D[2], Y[2]), f2mul(D[3], Y[3])));          \
        u64p g1 = f2add(f2add(f2mul(D[4], Y[4]), f2mul(D[5], Y[5])),           \
                        f2add(f2mul(D[6], Y[6]), f2mul(D[7], Y[7])));          \
        u64p gt = f2add(g0, g1);                                               \
        float lo, hi; upk2(gt, lo, hi);                                        \
        float s = lo + hi;                                                     \
        s += __shfl_xor_sync(0xffffffffu, s, 1);                               \
        s += __shfl_xor_sync(0xffffffffu, s, 2);                               \
        Wm2 = Wm1;                                                             \
        Wm1 = s;                                                               \
        if (r == 0) *op = fn;                                                  \
        op += B;                                                               \
        fx2 = f1;                                                              \
        f1 = fn;                                                               \
    }

    // Main loop: steps [0, T-8), refill rings at distance 8
    for (int t = 0; t < T - 8; t += 8) {
        #pragma unroll
        for (int k = 0; k < 8; k++) {
            float craw = cb[k];
            float cpre = cs[k];
            float cnew = *lp; lp += B;
            cb[k] = cnew;
            cs[k] = fmaf(cnew, SA, fmaf(clast, SDA, -gb));
            clast = cnew;
            FR_STEP(craw, cpre)
        }
    }
    // Epilogue: last 8 steps, no loads
    #pragma unroll
    for (int k = 0; k < 8; k++) {
        FR_STEP(cb[k], cs[k])
    }
    #undef FR_STEP
}

extern "C" void kernel_launch(void* const* d_in, const int* in_sizes, int n_in,
                              void* d_out, int out_size) {
    const float* cur = (const float*)d_in[0];   // currents [T*B]
    const float* fs0 = (const float*)d_in[1];   // [B]
    const float* av  = (const float*)d_in[2];   // [N]
    const float* bv  = (const float*)d_in[3];   // [N]
    const float* wv  = (const float*)d_in[4];   // [N,1]
    const float* dsv = (const float*)d_in[5];   // [N]
    const float* pc  = (const float*)d_in[6];   // [DEG+1]
    const float* gbp = (const float*)d_in[7];   // scalar

    int B = in_sizes[1];
    int T = in_sizes[0] / B;

    int threads = B * 4;                        // 4 lanes per chain
    int blocks = (threads + TPB - 1) / TPB;
    fr_kernel<<<blocks, TPB>>>(cur, fs0, av, bv, wv, dsv, pc, gbp,
                               (float*)d_out, T, B);
}